// round 1
// baseline (speedup 1.0000x reference)
#include <cuda_runtime.h>
#include <math.h>

#define BB 2
#define CC 256
#define HWN 6400
#define DD 32
#define PP 9

// ---------------- device scratch (no allocation allowed) ----------------
__device__ float g_qn[BB*DD*HWN];          // [b][d][i]  normalized q, transposed
__device__ float g_kn[BB*DD*HWN];          // [b][d][j]  normalized k, transposed
__device__ float g_v [BB*HWN*DD];          // [b][j][d]
__device__ float g_pval[BB*2*HWN*PP];      // partial top9 values per j-split
__device__ int   g_pidx[BB*2*HWN*PP];      // partial top9 indices
__device__ float g_ovb[BB*HWN*CC];         // [b][n][c]  catt * (ov @ back_w^T)

// ---------------- K1: q,k,v projections + L2 normalize ----------------
__global__ void __launch_bounds__(256) proj_kernel(
    const float* __restrict__ feat, const float* __restrict__ Wq,
    const float* __restrict__ Wk,   const float* __restrict__ Wv) {
  __shared__ float xs[64][33];     // [c_local][n]
  __shared__ float ws[96][64];     // [d][c_local]  (q:0-31, k:32-63, v:64-95)
  __shared__ float outs[96][33];   // [d][n]
  __shared__ float scl[2][32];
  int blk = blockIdx.x;
  int b  = blk / 200;
  int n0 = (blk % 200) * 32;
  int t  = threadIdx.x;
  int n  = t & 31, dg = t >> 5;    // dg 0..7 -> 12 d's each
  float acc[12];
#pragma unroll
  for (int u = 0; u < 12; u++) acc[u] = 0.f;

  for (int c0 = 0; c0 < CC; c0 += 64) {
#pragma unroll
    for (int r = 0; r < 8; r++) {
      int e = t + 256*r; int cl = e >> 5, nn = e & 31;
      xs[cl][nn] = feat[(b*CC + c0 + cl)*HWN + n0 + nn];
    }
#pragma unroll
    for (int r = 0; r < 24; r++) {
      int e = t + 256*r; int cl = e & 63, d = e >> 6;
      const float* Wp = (d < 32) ? Wq : ((d < 64) ? Wk : Wv);
      ws[d][cl] = Wp[(d & 31)*CC + c0 + cl];
    }
    __syncthreads();
#pragma unroll 4
    for (int cl = 0; cl < 64; cl += 4) {
      float x0 = xs[cl][n], x1 = xs[cl+1][n], x2 = xs[cl+2][n], x3 = xs[cl+3][n];
#pragma unroll
      for (int u = 0; u < 12; u++) {
        const float4 w4 = *(const float4*)&ws[dg*12+u][cl];
        acc[u] += w4.x*x0 + w4.y*x1 + w4.z*x2 + w4.w*x3;
      }
    }
    __syncthreads();
  }
#pragma unroll
  for (int u = 0; u < 12; u++) outs[dg*12+u][n] = acc[u];
  __syncthreads();
  if (t < 64) {
    int nn = t & 31, wh = t >> 5;
    float s = 0.f;
#pragma unroll
    for (int d = 0; d < 32; d++) { float v = outs[wh*32+d][nn]; s += v*v; }
    scl[wh][nn] = 1.f / fmaxf(sqrtf(s), 1e-12f);
  }
  __syncthreads();
#pragma unroll
  for (int r = 0; r < 4; r++) {
    int e = t + 256*r; int d = e >> 5, nn = e & 31;
    g_qn[(b*DD + d)*HWN + n0 + nn] = outs[d][nn]    * scl[0][nn];
    g_kn[(b*DD + d)*HWN + n0 + nn] = outs[32+d][nn] * scl[1][nn];
  }
#pragma unroll
  for (int r = 0; r < 4; r++) {
    int e = t + 256*r; int d = e & 31, nn = e >> 5;
    g_v[(b*HWN + n0 + nn)*DD + d] = outs[64+d][nn];
  }
}

// ---------------- K2: w = qn @ kn^T fused with top-9 per row ----------------
// 400 blocks: b x jsplit(2) x 100 i-tiles of 64. Each block scans 3200 j's.
__global__ void __launch_bounds__(256) wtopk_kernel() {
  __shared__ float qs[32][64];     // [k][i]
  __shared__ float ks[32][64];     // [k][j]
  __shared__ float w_s[64][65];    // staged tile for the scan
  int blk = blockIdx.x;
  int b = blk / 200; int rem = blk % 200;
  int split = rem / 100; int i0 = (rem % 100) * 64;
  int jbase = split * 3200;
  int t = threadIdx.x;
  int tx = t & 15, ty = t >> 4;    // 4 rows x 4 cols micro-tile

#pragma unroll
  for (int r = 0; r < 8; r++) {
    int e = t + 256*r; int i = e & 63, d = e >> 6;
    qs[d][i] = g_qn[(b*DD + d)*HWN + i0 + i];
  }
  float tv[9]; int ti[9];
#pragma unroll
  for (int s = 0; s < 9; s++) { tv[s] = -3.f; ti[s] = 0; }

  for (int jt = 0; jt < 50; jt++) {
    int j0 = jbase + jt*64;
#pragma unroll
    for (int r = 0; r < 8; r++) {
      int e = t + 256*r; int j = e & 63, d = e >> 6;
      ks[d][j] = g_kn[(b*DD + d)*HWN + j0 + j];
    }
    __syncthreads();
    float a00=0,a01=0,a02=0,a03=0, a10=0,a11=0,a12=0,a13=0;
    float a20=0,a21=0,a22=0,a23=0, a30=0,a31=0,a32=0,a33=0;
#pragma unroll
    for (int k = 0; k < 32; k++) {
      float4 av = *(const float4*)&qs[k][tx*4];
      float4 bv = *(const float4*)&ks[k][ty*4];
      a00 += av.x*bv.x; a01 += av.x*bv.y; a02 += av.x*bv.z; a03 += av.x*bv.w;
      a10 += av.y*bv.x; a11 += av.y*bv.y; a12 += av.y*bv.z; a13 += av.y*bv.w;
      a20 += av.z*bv.x; a21 += av.z*bv.y; a22 += av.z*bv.z; a23 += av.z*bv.w;
      a30 += av.w*bv.x; a31 += av.w*bv.y; a32 += av.w*bv.z; a33 += av.w*bv.w;
    }
    int rr = tx*4, cc = ty*4;
    w_s[rr+0][cc+0]=a00; w_s[rr+0][cc+1]=a01; w_s[rr+0][cc+2]=a02; w_s[rr+0][cc+3]=a03;
    w_s[rr+1][cc+0]=a10; w_s[rr+1][cc+1]=a11; w_s[rr+1][cc+2]=a12; w_s[rr+1][cc+3]=a13;
    w_s[rr+2][cc+0]=a20; w_s[rr+2][cc+1]=a21; w_s[rr+2][cc+2]=a22; w_s[rr+2][cc+3]=a23;
    w_s[rr+3][cc+0]=a30; w_s[rr+3][cc+1]=a31; w_s[rr+3][cc+2]=a32; w_s[rr+3][cc+3]=a33;
    __syncthreads();
    if (t < 64) {
      // thread t owns row i0+t; sorted-desc insertion, strict > keeps
      // jax.top_k's earlier-index-wins tie behavior (scan is ascending j).
      for (int c = 0; c < 64; c++) {
        float v = w_s[t][c];
        if (v > tv[8]) {
          float cv = v; int cj = j0 + c;
#pragma unroll
          for (int s = 0; s < 9; s++) {
            bool gt = cv > tv[s];
            float nv = gt ? cv : tv[s]; int ni = gt ? cj : ti[s];
            float sv = gt ? tv[s] : cv; int si = gt ? ti[s] : cj;
            tv[s] = nv; ti[s] = ni; cv = sv; cj = si;
          }
        }
      }
    }
    // no trailing barrier needed: next loadks only touches ks; the barrier
    // after it protects w_s before it is rewritten.
  }
  if (t < 64) {
    int row = i0 + t;
#pragma unroll
    for (int s = 0; s < 9; s++) {
      g_pval[((b*2 + split)*HWN + row)*PP + s] = tv[s];
      g_pidx[((b*2 + split)*HWN + row)*PP + s] = ti[s];
    }
  }
}

// ---------------- K3: merge splits + gate MLP + softmax + gather + back ----------------
__global__ void __launch_bounds__(256) post_kernel(
    const float* __restrict__ adw, const float* __restrict__ adb,
    const float* __restrict__ pw1, const float* __restrict__ pw2,
    const float* __restrict__ back_w, const float* __restrict__ catt) {
  __shared__ float back_s[256][33];
  __shared__ float w1s[162];
  __shared__ float w2s[162];
  __shared__ float wfin_s[8][12];
  __shared__ int   idx_s[8][12];
  int blk = blockIdx.x;
  int b = blk / 800;
  int row0 = (blk % 800) * 8;
  int t = threadIdx.x;
#pragma unroll
  for (int r = 0; r < 32; r++) {
    int e = t + 256*r; int c = e >> 5, d = e & 31;
    back_s[c][d] = back_w[c*DD + d];
  }
  if (t < 162) { w1s[t] = pw1[t]; w2s[t] = pw2[t]; }
  __syncthreads();
  int wrp = t >> 5, lane = t & 31;
  int row = row0 + wrp;

  if (lane == 0) {
    float va[9], vb[9]; int ia[9], ib[9];
#pragma unroll
    for (int s = 0; s < 9; s++) {
      va[s] = g_pval[((b*2+0)*HWN + row)*PP + s];
      ia[s] = g_pidx[((b*2+0)*HWN + row)*PP + s];
      vb[s] = g_pval[((b*2+1)*HWN + row)*PP + s];
      ib[s] = g_pidx[((b*2+1)*HWN + row)*PP + s];
    }
    float mv[9]; int mi[9];
    int pa = 0, pb = 0;
#pragma unroll
    for (int r = 0; r < 9; r++) {
      // tie -> list A (lower j indices by construction)
      bool takeA = (va[pa] >= vb[pb]);
      if (takeA) { mv[r] = va[pa]; mi[r] = ia[pa]; pa++; }
      else       { mv[r] = vb[pb]; mi[r] = ib[pb]; pb++; }
    }
    float adwv = adw[0], adbv = adb[0];
    float xa[9], pos[9];
#pragma unroll
    for (int p = 0; p < 9; p++) { xa[p] = mv[p]*adwv + adbv; pos[p] = fmaxf(xa[p], 0.f); }
    float hdn[18];
#pragma unroll
    for (int q = 0; q < 18; q++) {
      float s = 0.f;
#pragma unroll
      for (int p = 0; p < 9; p++) s += w1s[q*9+p]*pos[p];
      hdn[q] = fmaxf(s, 0.f);
    }
    float z[9]; float zmax = -1e30f;
#pragma unroll
    for (int p = 0; p < 9; p++) { z[p] = (xa[p] > 0.f) ? xa[p] : -100000.0f; zmax = fmaxf(zmax, z[p]); }
    float es[9]; float esum = 0.f;
#pragma unroll
    for (int p = 0; p < 9; p++) { es[p] = expf(z[p]-zmax); esum += es[p]; }
    float inv = 1.f/esum;
#pragma unroll
    for (int p = 0; p < 9; p++) {
      float s = 0.f;
#pragma unroll
      for (int q = 0; q < 18; q++) s += w2s[p*18+q]*hdn[q];
      float msk = 1.f/(1.f+expf(-s));
      wfin_s[wrp][p] = es[p]*inv*msk;
      idx_s[wrp][p]  = mi[p];
    }
  }
  __syncwarp();
  // ov[d]: lane = d
  float ov = 0.f;
#pragma unroll
  for (int p = 0; p < 9; p++)
    ov += wfin_s[wrp][p] * g_v[(b*HWN + idx_s[wrp][p])*DD + lane];
  // back-projection 256x32 via shuffle broadcast
  float outc[8];
#pragma unroll
  for (int cc = 0; cc < 8; cc++) outc[cc] = 0.f;
#pragma unroll
  for (int d = 0; d < 32; d++) {
    float ovd = __shfl_sync(0xffffffffu, ov, d);
#pragma unroll
    for (int cc = 0; cc < 8; cc++) outc[cc] += back_s[cc*32+lane][d]*ovd;
  }
#pragma unroll
  for (int cc = 0; cc < 8; cc++) {
    int c = cc*32 + lane;
    g_ovb[(b*HWN + row)*CC + c] = outc[cc]*catt[c];
  }
}

// ---------------- K4: mlp GEMM (512->256) + bias + BN(eval) + relu ----------------
__global__ void __launch_bounds__(256) mlp_kernel(
    const float* __restrict__ feat, const float* __restrict__ mlp_w,
    const float* __restrict__ mlp_b, const float* __restrict__ mlp_gamma,
    const float* __restrict__ mlp_beta, const float* __restrict__ catt1,
    float* __restrict__ xout) {
  __shared__ float a_s[32][68];   // [k][o]  (68: 16B-aligned rows for float4)
  __shared__ float b_s[32][68];   // [k][n]
  int blk = blockIdx.x;
  int b = blk / 400; int rem = blk % 400;
  int o0 = (rem / 100) * 64;
  int n0 = (rem % 100) * 64;
  int t = threadIdx.x;
  int tx = t & 15, ty = t >> 4;
  float a00=0,a01=0,a02=0,a03=0, a10=0,a11=0,a12=0,a13=0;
  float a20=0,a21=0,a22=0,a23=0, a30=0,a31=0,a32=0,a33=0;

  for (int k0 = 0; k0 < 512; k0 += 32) {
#pragma unroll
    for (int r = 0; r < 8; r++) {
      int e = t + 256*r; int kk = e & 31, oo = e >> 5;
      int kg = k0 + kk;
      float wv_ = mlp_w[(o0+oo)*512 + kg];
      if (kg >= 256) wv_ *= catt1[kg-256];
      a_s[kk][oo] = wv_;
    }
    if (k0 < 256) {
#pragma unroll
      for (int r = 0; r < 8; r++) {
        int e = t + 256*r; int kk = e & 31, nn = e >> 5;
        b_s[kk][nn] = g_ovb[(b*HWN + n0+nn)*CC + k0+kk];
      }
    } else {
#pragma unroll
      for (int r = 0; r < 8; r++) {
        int e = t + 256*r; int nn = e & 63, kk = e >> 6;
        b_s[kk][nn] = feat[(b*CC + (k0-256+kk))*HWN + n0+nn];
      }
    }
    __syncthreads();
#pragma unroll
    for (int k = 0; k < 32; k++) {
      float4 av = *(const float4*)&a_s[k][tx*4];
      float4 bv = *(const float4*)&b_s[k][ty*4];
      a00 += av.x*bv.x; a01 += av.x*bv.y; a02 += av.x*bv.z; a03 += av.x*bv.w;
      a10 += av.y*bv.x; a11 += av.y*bv.y; a12 += av.y*bv.z; a13 += av.y*bv.w;
      a20 += av.z*bv.x; a21 += av.z*bv.y; a22 += av.z*bv.z; a23 += av.z*bv.w;
      a30 += av.w*bv.x; a31 += av.w*bv.y; a32 += av.w*bv.z; a33 += av.w*bv.w;
    }
    __syncthreads();
  }
  const float bnadj = rsqrtf(1.0f + 1e-5f);
  float racc[4][4] = {{a00,a01,a02,a03},{a10,a11,a12,a13},{a20,a21,a22,a23},{a30,a31,a32,a33}};
#pragma unroll
  for (int u = 0; u < 4; u++) {
    int o = o0 + tx*4 + u;
    float g  = mlp_gamma[o]*bnadj;
    float be = mlp_beta[o];
    float mb = mlp_b[o];
    float4 res;
    res.x = fmaxf((racc[u][0]+mb)*g + be, 0.f);
    res.y = fmaxf((racc[u][1]+mb)*g + be, 0.f);
    res.z = fmaxf((racc[u][2]+mb)*g + be, 0.f);
    res.w = fmaxf((racc[u][3]+mb)*g + be, 0.f);
    *(float4*)&xout[(b*CC + o)*HWN + n0 + ty*4] = res;
  }
}

// ---------------- K5: dsn head (256->1) + BN + relu ----------------
__global__ void __launch_bounds__(256) dsn_kernel(
    const float* __restrict__ dsn_w, const float* __restrict__ dsn_b,
    const float* __restrict__ dsn_g, const float* __restrict__ dsn_beta,
    const float* __restrict__ x, float* __restrict__ r0) {
  __shared__ float ws[256];
  int blk = blockIdx.x;
  int b  = blk / 25;
  int n0 = (blk % 25) * 256;
  int t  = threadIdx.x;
  ws[t] = dsn_w[t];
  __syncthreads();
  int n = n0 + t;
  float acc = 0.f;
#pragma unroll 8
  for (int o = 0; o < 256; o++) acc += ws[o]*x[(b*CC+o)*HWN + n];
  float g = dsn_g[0]*rsqrtf(1.0f+1e-5f);
  r0[b*HWN + n] = fmaxf((acc + dsn_b[0])*g + dsn_beta[0], 0.f);
}

// ---------------- launch ----------------
extern "C" void kernel_launch(void* const* d_in, const int* in_sizes, int n_in,
                              void* d_out, int out_size) {
  const float* feat    = (const float*)d_in[0];
  const float* Wq      = (const float*)d_in[1];
  const float* Wk      = (const float*)d_in[2];
  const float* Wv      = (const float*)d_in[3];
  const float* adw     = (const float*)d_in[4];
  const float* adb     = (const float*)d_in[5];
  const float* pw1     = (const float*)d_in[6];
  const float* pw2     = (const float*)d_in[7];
  const float* backw   = (const float*)d_in[8];
  const float* catt    = (const float*)d_in[9];
  const float* catt1   = (const float*)d_in[10];
  const float* mlpw    = (const float*)d_in[11];
  const float* mlpb    = (const float*)d_in[12];
  const float* mlpg    = (const float*)d_in[13];
  const float* mlpbeta = (const float*)d_in[14];
  const float* dsnw    = (const float*)d_in[15];
  const float* dsnb    = (const float*)d_in[16];
  const float* dsng    = (const float*)d_in[17];
  const float* dsnbeta = (const float*)d_in[18];
  float* out = (float*)d_out;

  proj_kernel<<<400, 256>>>(feat, Wq, Wk, Wv);
  wtopk_kernel<<<400, 256>>>();
  post_kernel<<<1600, 256>>>(adw, adb, pw1, pw2, backw, catt);
  mlp_kernel<<<800, 256>>>(feat, mlpw, mlpb, mlpg, mlpbeta, catt1, out);
  dsn_kernel<<<50, 256>>>(dsnw, dsnb, dsng, dsnbeta, out, out + BB*CC*HWN);
}